// round 9
// baseline (speedup 1.0000x reference)
#include <cuda_runtime.h>

#define SS 2048
#define RR 384

typedef unsigned long long ull;

// ---- device scratch (no allocs allowed) ----
__device__ float g_kv[RR * 16 * SS];     // [r][c][s]; c: 0-7 = k, 8-15 = v
__device__ float g_maskT[RR * SS];       // transposed mask [r][s]
__device__ float g_qpart[RR * 16 * 68];  // per-(r, s-block) partials
__device__ float g_o[RR * 64];           // attention output per r  [h*8+c]
// LN-folded weights
__device__ float g_AW[16 * 64];          // [c][d] = g[d]*Wkv[d][c]
__device__ float g_S1kv[16];
__device__ float g_bkv[16];
__device__ float g_GW[64 * 64];          // [j][d] = g[d]*Wg[d][j]
__device__ float g_S1g[64];
__device__ float g_bG[64];               // bg[j] + sum_d b[d]*Wg[d][j]
__device__ float g_WoT[64 * 64];         // [d][j] = Wo[j][d]

// ---- packed fp32x2 helpers (Blackwell FFMA2) ----
__device__ __forceinline__ ull ffma2(ull a, ull b, ull c) {
    ull d;
    asm("fma.rn.f32x2 %0, %1, %2, %3;" : "=l"(d) : "l"(a), "l"(b), "l"(c));
    return d;
}
__device__ __forceinline__ float2 upk(ull v) {
    float2 f; asm("mov.b64 {%0,%1}, %2;" : "=f"(f.x), "=f"(f.y) : "l"(v)); return f;
}
__device__ __forceinline__ ull pk2(float lo, float hi) {
    ull r; asm("mov.b64 %0, {%1,%2};" : "=l"(r) : "f"(lo), "f"(hi)); return r;
}

// ---------------------------------------------------------------------------
// Kernel DP: mask transpose (blocks 0..767) + weight folding (block 768)
// ---------------------------------------------------------------------------
__global__ __launch_bounds__(256) void kernelDP(
    const float* __restrict__ Mmask,
    const float* __restrict__ lng, const float* __restrict__ lnb,
    const float* __restrict__ Wk, const float* __restrict__ Wv,
    const float* __restrict__ Wg, const float* __restrict__ bg,
    const float* __restrict__ Wo)
{
    const int tid = threadIdx.x;
    if (blockIdx.x < 768) {
        // mask transpose [S][R] -> [R][S]
        __shared__ float t[32][33];
        const int bx = blockIdx.x % 12, by = blockIdx.x / 12;
        const int tx = tid & 31, ty = tid >> 5;
        const int r0 = bx * 32, s0 = by * 32;
        #pragma unroll
        for (int k = 0; k < 32; k += 8)
            t[ty + k][tx] = Mmask[(s0 + ty + k) * RR + r0 + tx];
        __syncthreads();
        #pragma unroll
        for (int k = 0; k < 32; k += 8)
            g_maskT[(r0 + ty + k) * SS + s0 + tx] = t[tx][ty + k];
    } else {
        // fold LayerNorm gamma/beta into weights
        for (int i = tid; i < 16 * 64; i += 256) {
            int c = i >> 6, d = i & 63;
            float w = (c < 8) ? Wk[d * 8 + c] : Wv[d * 8 + c - 8];
            g_AW[i] = lng[d] * w;
        }
        for (int i = tid; i < 64 * 64; i += 256) {
            int a = i >> 6, b = i & 63;
            g_GW[i]  = lng[b] * Wg[b * 64 + a];   // [j=a][d=b]
            g_WoT[i] = Wo[b * 64 + a];            // [d=a][j=b]
        }
        __syncthreads();
        if (tid < 16) {
            float s1 = 0.f, bb = 0.f;
            for (int d = 0; d < 64; ++d) {
                s1 += g_AW[tid * 64 + d];
                float w = (tid < 8) ? Wk[d * 8 + tid] : Wv[d * 8 + tid - 8];
                bb += lnb[d] * w;
            }
            g_S1kv[tid] = s1; g_bkv[tid] = bb;
        }
        if (tid >= 64 && tid < 128) {
            int j = tid - 64;
            float s1 = 0.f, bb = 0.f;
            for (int d = 0; d < 64; ++d) {
                s1 += g_GW[j * 64 + d];
                bb += lnb[d] * Wg[d * 64 + j];
            }
            g_S1g[j] = s1; g_bG[j] = bg[j] + bb;
        }
    }
}

// ---------------------------------------------------------------------------
// Kernel A: rows-in-lanes LN (folded) + k/v projection + masked-q partials
// (exact R2 version — best measured)
// ---------------------------------------------------------------------------
__global__ __launch_bounds__(128) void kernelA(const float* __restrict__ M) {
    __shared__ __align__(16) float stage[4][32][68];
    __shared__ __align__(16) float sAW[16][68];
    __shared__ float sS1[16], sbk[16];
    __shared__ float sQ[4][68];
    const int tid = threadIdx.x, w = tid >> 5, t = tid & 31;
    const int r = blockIdx.y;
    const int srow = blockIdx.x * 128 + w * 32;

    for (int i = tid; i < 16 * 64; i += 128) { int c = i >> 6, d = i & 63; sAW[c][d] = g_AW[i]; }
    if (tid < 16) { sS1[tid] = g_S1kv[tid]; sbk[tid] = g_bkv[tid]; }
    __syncthreads();

    const int cr = t >> 4, cc = (t & 15) * 4;
    #pragma unroll
    for (int i = 0; i < 16; ++i) {
        int rr = i * 2 + cr;
        *(float4*)&stage[w][rr][cc] =
            *(const float4*)&M[(((srow + rr) * RR) + r) * 64 + cc];
    }
    __syncwarp();

    ull xp[32];
    {
        const ulonglong2* rp = (const ulonglong2*)&stage[w][t][0];
        #pragma unroll
        for (int i = 0; i < 16; ++i) { ulonglong2 v = rp[i]; xp[2 * i] = v.x; xp[2 * i + 1] = v.y; }
    }
    float sum = 0.f, sq = 0.f;
    #pragma unroll
    for (int i = 0; i < 32; ++i) { float2 f = upk(xp[i]); sum += f.x + f.y; sq += f.x * f.x + f.y * f.y; }
    const float mu = sum * (1.f / 64.f);
    const float rstd = rsqrtf(sq * (1.f / 64.f) - mu * mu + 1e-5f);
    const int s = srow + t;
    const float mk = g_maskT[r * SS + s];

    // k/v projection (LN folded)
    #pragma unroll
    for (int c = 0; c < 16; ++c) {
        const ulonglong2* wp_ = (const ulonglong2*)&sAW[c][0];
        ull a0 = 0ull, a1 = 0ull;
        #pragma unroll
        for (int i = 0; i < 16; ++i) {
            ulonglong2 v = wp_[i];
            a0 = ffma2(xp[2 * i], v.x, a0);
            a1 = ffma2(xp[2 * i + 1], v.y, a1);
        }
        float2 f0 = upk(a0), f1 = upk(a1);
        float dot = f0.x + f0.y + f1.x + f1.y;
        g_kv[((r * 16 + c) * SS) + s] = rstd * (dot - mu * sS1[c]) + sbk[c];
    }

    // masked-query partial rows -> reuse tile, then column-reduce
    {
        const float mkr = mk * rstd;
        const ull mp = pk2(mkr, mkr);
        float4* qr = (float4*)&stage[w][t][0];
        #pragma unroll
        for (int i = 0; i < 16; ++i) {
            float2 a = upk(ffma2(xp[2 * i], mp, 0ull));
            float2 b = upk(ffma2(xp[2 * i + 1], mp, 0ull));
            qr[i] = make_float4(a.x, a.y, b.x, b.y);
        }
        stage[w][t][64] = mkr * mu;  // Pmu contribution
        stage[w][t][65] = mk;        // Pc contribution
    }
    __syncwarp();
    {
        float ax = 0.f, ay = 0.f;
        #pragma unroll
        for (int rr = 0; rr < 32; ++rr) {
            float2 v = *(const float2*)&stage[w][rr][2 * t];
            ax += v.x; ay += v.y;
        }
        sQ[w][2 * t] = ax; sQ[w][2 * t + 1] = ay;
        if (t < 2) {
            float e = 0.f;
            #pragma unroll
            for (int rr = 0; rr < 32; ++rr) e += stage[w][rr][64 + t];
            sQ[w][64 + t] = e;
        }
    }
    __syncthreads();
    if (tid < 66) {
        float a = sQ[0][tid] + sQ[1][tid] + sQ[2][tid] + sQ[3][tid];
        g_qpart[(r * 16 + blockIdx.x) * 68 + tid] = a;
    }
}

// ---------------------------------------------------------------------------
// Kernel B: pooled q, two-pass streaming softmax over S (52us version)
// ---------------------------------------------------------------------------
__global__ __launch_bounds__(256) void kernelB(
    const float* __restrict__ Wq, const float* __restrict__ lng,
    const float* __restrict__ lnb)
{
    __shared__ float sqa[68];
    __shared__ float sq[64];
    __shared__ float smax[8];
    __shared__ float red[8][80];
    const int tid = threadIdx.x, w = tid >> 5, t = tid & 31, r = blockIdx.x;

    if (tid < 66) {
        float a = 0.f;
        #pragma unroll
        for (int c = 0; c < 16; ++c) a += g_qpart[(r * 16 + c) * 68 + tid];
        sqa[tid] = a;
    }
    __syncthreads();
    if (tid < 64) {
        float Pmu = sqa[64], Pc = sqa[65];
        sqa[tid] = (lng[tid] * (sqa[tid] - Pmu) + lnb[tid] * Pc) / (Pc + 1e-10f);
    }
    __syncthreads();
    if (tid < 64) {
        float acc = 0.f;
        #pragma unroll
        for (int d = 0; d < 64; ++d) acc += sqa[d] * Wq[d * 64 + tid];
        sq[tid] = acc * 0.35355339059327373f;
    }
    __syncthreads();

    // pass 1: per-head max
    float mx[8];
    #pragma unroll
    for (int h = 0; h < 8; ++h) mx[h] = -3.0e38f;
    for (int s = tid; s < SS; s += 256) {
        float kk[8];
        #pragma unroll
        for (int c = 0; c < 8; ++c) kk[c] = g_kv[((r * 16 + c) * SS) + s];
        float bias = 1e9f * (g_maskT[r * SS + s] - 1.f);
        #pragma unroll
        for (int h = 0; h < 8; ++h) {
            float lg = bias;
            #pragma unroll
            for (int c = 0; c < 8; ++c) lg += sq[h * 8 + c] * kk[c];
            mx[h] = fmaxf(mx[h], lg);
        }
    }
    #pragma unroll
    for (int h = 0; h < 8; ++h) {
        #pragma unroll
        for (int o = 16; o > 0; o >>= 1) mx[h] = fmaxf(mx[h], __shfl_xor_sync(0xffffffffu, mx[h], o));
    }
    if (t < 8) red[w][t] = mx[t];
    __syncthreads();
    if (tid < 8) {
        float m = red[0][tid];
        #pragma unroll
        for (int ww = 1; ww < 8; ++ww) m = fmaxf(m, red[ww][tid]);
        smax[tid] = m;
    }
    __syncthreads();

    // pass 2: exp + weighted-v accumulation
    float Z[8];
    float acc[64];
    #pragma unroll
    for (int h = 0; h < 8; ++h) Z[h] = 0.f;
    #pragma unroll
    for (int i = 0; i < 64; ++i) acc[i] = 0.f;
    for (int s = tid; s < SS; s += 256) {
        float kk[8], vv[8];
        #pragma unroll
        for (int c = 0; c < 8; ++c) kk[c] = g_kv[((r * 16 + c) * SS) + s];
        #pragma unroll
        for (int c = 0; c < 8; ++c) vv[c] = g_kv[((r * 16 + 8 + c) * SS) + s];
        float bias = 1e9f * (g_maskT[r * SS + s] - 1.f);
        #pragma unroll
        for (int h = 0; h < 8; ++h) {
            float lg = bias;
            #pragma unroll
            for (int c = 0; c < 8; ++c) lg += sq[h * 8 + c] * kk[c];
            float e = __expf(lg - smax[h]);
            Z[h] += e;
            #pragma unroll
            for (int c = 0; c < 8; ++c) acc[h * 8 + c] += e * vv[c];
        }
    }
    #pragma unroll
    for (int i = 0; i < 64; ++i) {
        float v = acc[i];
        #pragma unroll
        for (int o = 16; o > 0; o >>= 1) v += __shfl_xor_sync(0xffffffffu, v, o);
        if (t == 0) red[w][i] = v;
    }
    #pragma unroll
    for (int h = 0; h < 8; ++h) {
        float v = Z[h];
        #pragma unroll
        for (int o = 16; o > 0; o >>= 1) v += __shfl_xor_sync(0xffffffffu, v, o);
        if (t == 0) red[w][64 + h] = v;
    }
    __syncthreads();
    if (tid < 72) {
        float v = 0.f;
        #pragma unroll
        for (int ww = 0; ww < 8; ++ww) v += red[ww][tid];
        red[0][tid] = v;
    }
    __syncthreads();
    if (tid < 64) g_o[r * 64 + tid] = red[0][tid] / red[0][64 + (tid >> 3)];
}

// ---------------------------------------------------------------------------
// Kernel C (exact R2/653us version, r-sliced): rows-in-lanes, smem weights,
// FFMA2. grid (4, 128) per slice; r = r0 + blockIdx.y.
// ---------------------------------------------------------------------------
__global__ __launch_bounds__(128) void kernelC(
    const float* __restrict__ M, const float* __restrict__ bo,
    float* __restrict__ outp, int r0)
{
    extern __shared__ __align__(16) float dyn[];
    float* stage = dyn;                     // [4][32][68]
    float* sGW   = dyn + 4 * 32 * 68;       // [64][68]
    float* sWoT  = sGW + 64 * 68;           // [64][68]
    float* so    = sWoT + 64 * 68;          // [64]
    float* sS1g  = so + 64;                 // [64]
    float* sbG   = sS1g + 64;               // [64]
    float* sbo   = sbG + 64;                // [64]
    const int tid = threadIdx.x, w = tid >> 5, t = tid & 31;
    const int r = r0 + blockIdx.y;

    for (int i = tid; i < 4096; i += 128) {
        int j = i >> 6, d = i & 63;
        sGW[j * 68 + d]  = g_GW[i];
        sWoT[j * 68 + d] = g_WoT[i];
    }
    if (tid < 64) {
        so[tid] = g_o[r * 64 + tid];
        sS1g[tid] = g_S1g[tid]; sbG[tid] = g_bG[tid]; sbo[tid] = bo[tid];
    }
    __syncthreads();

    float* tile = stage + w * 32 * 68;
    const int cr = t >> 4, cc = (t & 15) * 4;

    for (int sub = 0; sub < 4; ++sub) {
        const int srow = blockIdx.x * 512 + sub * 128 + w * 32;
        #pragma unroll
        for (int i = 0; i < 16; ++i) {
            int rr = i * 2 + cr;
            *(float4*)&tile[rr * 68 + cc] =
                *(const float4*)&M[(((srow + rr) * RR) + r) * 64 + cc];
        }
        __syncwarp();

        ull xp[32];
        {
            const ulonglong2* rp = (const ulonglong2*)&tile[t * 68];
            #pragma unroll
            for (int i = 0; i < 16; ++i) { ulonglong2 v = rp[i]; xp[2 * i] = v.x; xp[2 * i + 1] = v.y; }
        }
        float sum = 0.f, sq = 0.f;
        #pragma unroll
        for (int i = 0; i < 32; ++i) { float2 f = upk(xp[i]); sum += f.x + f.y; sq += f.x * f.x + f.y * f.y; }
        const float mu = sum * (1.f / 64.f);
        const float rstd = rsqrtf(sq * (1.f / 64.f) - mu * mu + 1e-5f);

        // gate: g[j] = sigmoid(rstd*(x.GW[j] - mu*S1g[j]) + bG[j]); ghat = g*o
        ull gp[32];
        #pragma unroll
        for (int jp = 0; jp < 32; ++jp) {
            const ulonglong2* wa = (const ulonglong2*)&sGW[(2 * jp) * 68];
            const ulonglong2* wb = (const ulonglong2*)&sGW[(2 * jp + 1) * 68];
            ull a0 = 0ull, a1 = 0ull, b0 = 0ull, b1 = 0ull;
            #pragma unroll
            for (int i = 0; i < 16; ++i) {
                ulonglong2 va = wa[i], vb = wb[i];
                a0 = ffma2(xp[2 * i], va.x, a0); a1 = ffma2(xp[2 * i + 1], va.y, a1);
                b0 = ffma2(xp[2 * i], vb.x, b0); b1 = ffma2(xp[2 * i + 1], vb.y, b1);
            }
            float2 fa0 = upk(a0), fa1 = upk(a1), fb0 = upk(b0), fb1 = upk(b1);
            float da = fa0.x + fa0.y + fa1.x + fa1.y;
            float db = fb0.x + fb0.y + fb1.x + fb1.y;
            float aga = rstd * (da - mu * sS1g[2 * jp])     + sbG[2 * jp];
            float agb = rstd * (db - mu * sS1g[2 * jp + 1]) + sbG[2 * jp + 1];
            float ga = 1.f / (1.f + __expf(-aga));
            float gb = 1.f / (1.f + __expf(-agb));
            float2 oo = *(const float2*)&so[2 * jp];
            gp[jp] = pk2(ga * oo.x, gb * oo.y);
        }

        // out[d] = sum_j ghat[j]*Wo[j][d] + bo[d] + x[d]
        #pragma unroll
        for (int dp = 0; dp < 32; ++dp) {
            const ulonglong2* wa = (const ulonglong2*)&sWoT[(2 * dp) * 68];
            const ulonglong2* wb = (const ulonglong2*)&sWoT[(2 * dp + 1) * 68];
            ull a0 = 0ull, a1 = 0ull, b0 = 0ull, b1 = 0ull;
            #pragma unroll
            for (int i = 0; i < 16; ++i) {
                ulonglong2 va = wa[i], vb = wb[i];
                a0 = ffma2(gp[2 * i], va.x, a0); a1 = ffma2(gp[2 * i + 1], va.y, a1);
                b0 = ffma2(gp[2 * i], vb.x, b0); b1 = ffma2(gp[2 * i + 1], vb.y, b1);
            }
            float2 fa0 = upk(a0), fa1 = upk(a1), fb0 = upk(b0), fb1 = upk(b1);
            float2 xr = upk(xp[dp]);
            float o0 = fa0.x + fa0.y + fa1.x + fa1.y + sbo[2 * dp]     + xr.x;
            float o1 = fb0.x + fb0.y + fb1.x + fb1.y + sbo[2 * dp + 1] + xr.y;
            *(float2*)&tile[t * 68 + 2 * dp] = make_float2(o0, o1);
        }
        __syncwarp();
        #pragma unroll
        for (int i = 0; i < 16; ++i) {
            int rr = i * 2 + cr;
            *(float4*)&outp[(((srow + rr) * RR) + r) * 64 + cc] =
                *(const float4*)&tile[rr * 68 + cc];
        }
        __syncwarp();
    }
}

// ---------------------------------------------------------------------------
extern "C" void kernel_launch(void* const* d_in, const int* in_sizes, int n_in,
                              void* d_out, int out_size)
{
    (void)in_sizes; (void)n_in; (void)out_size;
    const float* M    = (const float*)d_in[0];
    const float* mask = (const float*)d_in[1];
    const float* ln_g = (const float*)d_in[2];
    const float* ln_b = (const float*)d_in[3];
    const float* Wq   = (const float*)d_in[4];
    const float* Wk   = (const float*)d_in[5];
    const float* Wv   = (const float*)d_in[6];
    const float* Wg   = (const float*)d_in[7];
    const float* bg   = (const float*)d_in[8];
    const float* Wo   = (const float*)d_in[9];
    const float* bo   = (const float*)d_in[10];
    float* outp = (float*)d_out;

    const int smemC = (4 * 32 * 68 + 2 * 64 * 68 + 4 * 64) * 4;  // 70656 B
    cudaFuncSetAttribute(kernelC, cudaFuncAttributeMaxDynamicSharedMemorySize, smemC);

    kernelDP<<<769, 256>>>(mask, ln_g, ln_b, Wk, Wv, Wg, bg, Wo);
    kernelA<<<dim3(16, 384), 128>>>(M);
    kernelB<<<384, 256>>>(Wq, ln_g, ln_b);
    kernelC<<<dim3(4, 128), 128, smemC>>>(M, bo, outp, 0);
    kernelC<<<dim3(4, 128), 128, smemC>>>(M, bo, outp, 128);
    kernelC<<<dim3(4, 128), 128, smemC>>>(M, bo, outp, 256);
}

// round 12
// speedup vs baseline: 1.8882x; 1.8882x over previous
#include <cuda_runtime.h>
#include <cstdint>

#define SS 2048
#define RR 384

typedef unsigned long long ull;

// ---- device scratch (no allocs allowed) ----
__device__ float g_kv[RR * 16 * SS];     // [r][c][s]; c: 0-7 = k, 8-15 = v
__device__ float g_maskT[RR * SS];       // transposed mask [r][s]
__device__ float g_qpart[RR * 16 * 68];  // per-(r, s-block) partials
__device__ float g_o[RR * 64];           // attention output per r  [h*8+c]
__device__ float2 g_stats[RR * SS];      // per-row (mu, rstd), [r][s] layout
// LN-folded weights
__device__ float g_AW[16 * 64];          // [c][d] = g[d]*Wkv[d][c]
__device__ float g_S1kv[16];
__device__ float g_bkv[16];
__device__ float g_GW[64 * 64];          // [j][d] = g[d]*Wg[d][j]
__device__ float g_S1g[64];
__device__ float g_bG[64];               // bg[j] + sum_d b[d]*Wg[d][j]
__device__ float g_WoT[64 * 64];         // [d][j] = Wo[j][d]

// ---- packed fp32x2 helpers ----
__device__ __forceinline__ ull ffma2(ull a, ull b, ull c) {
    ull d;
    asm("fma.rn.f32x2 %0, %1, %2, %3;" : "=l"(d) : "l"(a), "l"(b), "l"(c));
    return d;
}
__device__ __forceinline__ float2 upk(ull v) {
    float2 f; asm("mov.b64 {%0,%1}, %2;" : "=f"(f.x), "=f"(f.y) : "l"(v)); return f;
}
__device__ __forceinline__ ull pk2(float lo, float hi) {
    ull r; asm("mov.b64 %0, {%1,%2};" : "=l"(r) : "f"(lo), "f"(hi)); return r;
}

// ---- warp MMA helpers (arch-legal on compute_103: no 'a' features) ----
__device__ __forceinline__ uint32_t f2tf32(float x) {
    uint32_t r; asm("cvt.rna.tf32.f32 %0, %1;" : "=r"(r) : "f"(x)); return r;
}
__device__ __forceinline__ void mma_tf32(float* d, const uint32_t* a,
                                         uint32_t b0, uint32_t b1) {
    asm volatile(
        "mma.sync.aligned.m16n8k8.row.col.f32.tf32.tf32.f32 "
        "{%0,%1,%2,%3}, {%4,%5,%6,%7}, {%8,%9}, {%0,%1,%2,%3};"
        : "+f"(d[0]), "+f"(d[1]), "+f"(d[2]), "+f"(d[3])
        : "r"(a[0]), "r"(a[1]), "r"(a[2]), "r"(a[3]), "r"(b0), "r"(b1));
}

// ---------------------------------------------------------------------------
// Kernel DP: mask transpose (blocks 0..767) + weight folding (block 768)
// ---------------------------------------------------------------------------
__global__ __launch_bounds__(256) void kernelDP(
    const float* __restrict__ Mmask,
    const float* __restrict__ lng, const float* __restrict__ lnb,
    const float* __restrict__ Wk, const float* __restrict__ Wv,
    const float* __restrict__ Wg, const float* __restrict__ bg,
    const float* __restrict__ Wo)
{
    const int tid = threadIdx.x;
    if (blockIdx.x < 768) {
        __shared__ float t[32][33];
        const int bx = blockIdx.x % 12, by = blockIdx.x / 12;
        const int tx = tid & 31, ty = tid >> 5;
        const int r0 = bx * 32, s0 = by * 32;
        #pragma unroll
        for (int k = 0; k < 32; k += 8)
            t[ty + k][tx] = Mmask[(s0 + ty + k) * RR + r0 + tx];
        __syncthreads();
        #pragma unroll
        for (int k = 0; k < 32; k += 8)
            g_maskT[(r0 + ty + k) * SS + s0 + tx] = t[tx][ty + k];
    } else {
        for (int i = tid; i < 16 * 64; i += 256) {
            int c = i >> 6, d = i & 63;
            float w = (c < 8) ? Wk[d * 8 + c] : Wv[d * 8 + c - 8];
            g_AW[i] = lng[d] * w;
        }
        for (int i = tid; i < 64 * 64; i += 256) {
            int a = i >> 6, b = i & 63;
            g_GW[i]  = lng[b] * Wg[b * 64 + a];   // [j=a][d=b]
            g_WoT[i] = Wo[b * 64 + a];            // [d=a][j=b]
        }
        __syncthreads();
        if (tid < 16) {
            float s1 = 0.f, bb = 0.f;
            for (int d = 0; d < 64; ++d) {
                s1 += g_AW[tid * 64 + d];
                float w = (tid < 8) ? Wk[d * 8 + tid] : Wv[d * 8 + tid - 8];
                bb += lnb[d] * w;
            }
            g_S1kv[tid] = s1; g_bkv[tid] = bb;
        }
        if (tid >= 64 && tid < 128) {
            int j = tid - 64;
            float s1 = 0.f, bb = 0.f;
            for (int d = 0; d < 64; ++d) {
                s1 += g_GW[j * 64 + d];
                bb += lnb[d] * Wg[d * 64 + j];
            }
            g_S1g[j] = s1; g_bG[j] = bg[j] + bb;
        }
    }
}

// ---------------------------------------------------------------------------
// Kernel A: rows-in-lanes LN (folded) + k/v projection + masked-q partials
// + stores per-row (mu, rstd) to g_stats[r][s] for kernelC
// ---------------------------------------------------------------------------
__global__ __launch_bounds__(128) void kernelA(const float* __restrict__ M) {
    __shared__ __align__(16) float stage[4][32][68];
    __shared__ __align__(16) float sAW[16][68];
    __shared__ float sS1[16], sbk[16];
    __shared__ float sQ[4][68];
    const int tid = threadIdx.x, w = tid >> 5, t = tid & 31;
    const int r = blockIdx.y;
    const int srow = blockIdx.x * 128 + w * 32;

    for (int i = tid; i < 16 * 64; i += 128) { int c = i >> 6, d = i & 63; sAW[c][d] = g_AW[i]; }
    if (tid < 16) { sS1[tid] = g_S1kv[tid]; sbk[tid] = g_bkv[tid]; }
    __syncthreads();

    const int cr = t >> 4, cc = (t & 15) * 4;
    #pragma unroll
    for (int i = 0; i < 16; ++i) {
        int rr = i * 2 + cr;
        *(float4*)&stage[w][rr][cc] =
            *(const float4*)&M[(((srow + rr) * RR) + r) * 64 + cc];
    }
    __syncwarp();

    ull xp[32];
    {
        const ulonglong2* rp = (const ulonglong2*)&stage[w][t][0];
        #pragma unroll
        for (int i = 0; i < 16; ++i) { ulonglong2 v = rp[i]; xp[2 * i] = v.x; xp[2 * i + 1] = v.y; }
    }
    float sum = 0.f, sq = 0.f;
    #pragma unroll
    for (int i = 0; i < 32; ++i) { float2 f = upk(xp[i]); sum += f.x + f.y; sq += f.x * f.x + f.y * f.y; }
    const float mu = sum * (1.f / 64.f);
    const float rstd = rsqrtf(sq * (1.f / 64.f) - mu * mu + 1e-5f);
    const int s = srow + t;
    const float mk = g_maskT[r * SS + s];
    g_stats[(size_t)r * SS + s] = make_float2(mu, rstd);

    #pragma unroll
    for (int c = 0; c < 16; ++c) {
        const ulonglong2* wp_ = (const ulonglong2*)&sAW[c][0];
        ull a0 = 0ull, a1 = 0ull;
        #pragma unroll
        for (int i = 0; i < 16; ++i) {
            ulonglong2 v = wp_[i];
            a0 = ffma2(xp[2 * i], v.x, a0);
            a1 = ffma2(xp[2 * i + 1], v.y, a1);
        }
        float2 f0 = upk(a0), f1 = upk(a1);
        float dot = f0.x + f0.y + f1.x + f1.y;
        g_kv[((r * 16 + c) * SS) + s] = rstd * (dot - mu * sS1[c]) + sbk[c];
    }

    {
        const float mkr = mk * rstd;
        const ull mp = pk2(mkr, mkr);
        float4* qr = (float4*)&stage[w][t][0];
        #pragma unroll
        for (int i = 0; i < 16; ++i) {
            float2 a = upk(ffma2(xp[2 * i], mp, 0ull));
            float2 b = upk(ffma2(xp[2 * i + 1], mp, 0ull));
            qr[i] = make_float4(a.x, a.y, b.x, b.y);
        }
        stage[w][t][64] = mkr * mu;
        stage[w][t][65] = mk;
    }
    __syncwarp();
    {
        float ax = 0.f, ay = 0.f;
        #pragma unroll
        for (int rr = 0; rr < 32; ++rr) {
            float2 v = *(const float2*)&stage[w][rr][2 * t];
            ax += v.x; ay += v.y;
        }
        sQ[w][2 * t] = ax; sQ[w][2 * t + 1] = ay;
        if (t < 2) {
            float e = 0.f;
            #pragma unroll
            for (int rr = 0; rr < 32; ++rr) e += stage[w][rr][64 + t];
            sQ[w][64 + t] = e;
        }
    }
    __syncthreads();
    if (tid < 66) {
        float a = sQ[0][tid] + sQ[1][tid] + sQ[2][tid] + sQ[3][tid];
        g_qpart[(r * 16 + blockIdx.x) * 68 + tid] = a;
    }
}

// ---------------------------------------------------------------------------
// Kernel B: pooled q, two-pass streaming softmax over S (52us version)
// ---------------------------------------------------------------------------
__global__ __launch_bounds__(256) void kernelB(
    const float* __restrict__ Wq, const float* __restrict__ lng,
    const float* __restrict__ lnb)
{
    __shared__ float sqa[68];
    __shared__ float sq[64];
    __shared__ float smax[8];
    __shared__ float red[8][80];
    const int tid = threadIdx.x, w = tid >> 5, t = tid & 31, r = blockIdx.x;

    if (tid < 66) {
        float a = 0.f;
        #pragma unroll
        for (int c = 0; c < 16; ++c) a += g_qpart[(r * 16 + c) * 68 + tid];
        sqa[tid] = a;
    }
    __syncthreads();
    if (tid < 64) {
        float Pmu = sqa[64], Pc = sqa[65];
        sqa[tid] = (lng[tid] * (sqa[tid] - Pmu) + lnb[tid] * Pc) / (Pc + 1e-10f);
    }
    __syncthreads();
    if (tid < 64) {
        float acc = 0.f;
        #pragma unroll
        for (int d = 0; d < 64; ++d) acc += sqa[d] * Wq[d * 64 + tid];
        sq[tid] = acc * 0.35355339059327373f;
    }
    __syncthreads();

    float mx[8];
    #pragma unroll
    for (int h = 0; h < 8; ++h) mx[h] = -3.0e38f;
    for (int s = tid; s < SS; s += 256) {
        float kk[8];
        #pragma unroll
        for (int c = 0; c < 8; ++c) kk[c] = g_kv[((r * 16 + c) * SS) + s];
        float bias = 1e9f * (g_maskT[r * SS + s] - 1.f);
        #pragma unroll
        for (int h = 0; h < 8; ++h) {
            float lg = bias;
            #pragma unroll
            for (int c = 0; c < 8; ++c) lg += sq[h * 8 + c] * kk[c];
            mx[h] = fmaxf(mx[h], lg);
        }
    }
    #pragma unroll
    for (int h = 0; h < 8; ++h) {
        #pragma unroll
        for (int o = 16; o > 0; o >>= 1) mx[h] = fmaxf(mx[h], __shfl_xor_sync(0xffffffffu, mx[h], o));
    }
    if (t < 8) red[w][t] = mx[t];
    __syncthreads();
    if (tid < 8) {
        float m = red[0][tid];
        #pragma unroll
        for (int ww = 1; ww < 8; ++ww) m = fmaxf(m, red[ww][tid]);
        smax[tid] = m;
    }
    __syncthreads();

    float Z[8];
    float acc[64];
    #pragma unroll
    for (int h = 0; h < 8; ++h) Z[h] = 0.f;
    #pragma unroll
    for (int i = 0; i < 64; ++i) acc[i] = 0.f;
    for (int s = tid; s < SS; s += 256) {
        float kk[8], vv[8];
        #pragma unroll
        for (int c = 0; c < 8; ++c) kk[c] = g_kv[((r * 16 + c) * SS) + s];
        #pragma unroll
        for (int c = 0; c < 8; ++c) vv[c] = g_kv[((r * 16 + 8 + c) * SS) + s];
        float bias = 1e9f * (g_maskT[r * SS + s] - 1.f);
        #pragma unroll
        for (int h = 0; h < 8; ++h) {
            float lg = bias;
            #pragma unroll
            for (int c = 0; c < 8; ++c) lg += sq[h * 8 + c] * kk[c];
            float e = __expf(lg - smax[h]);
            Z[h] += e;
            #pragma unroll
            for (int c = 0; c < 8; ++c) acc[h * 8 + c] += e * vv[c];
        }
    }
    #pragma unroll
    for (int i = 0; i < 64; ++i) {
        float v = acc[i];
        #pragma unroll
        for (int o = 16; o > 0; o >>= 1) v += __shfl_xor_sync(0xffffffffu, v, o);
        if (t == 0) red[w][i] = v;
    }
    #pragma unroll
    for (int h = 0; h < 8; ++h) {
        float v = Z[h];
        #pragma unroll
        for (int o = 16; o > 0; o >>= 1) v += __shfl_xor_sync(0xffffffffu, v, o);
        if (t == 0) red[w][64 + h] = v;
    }
    __syncthreads();
    if (tid < 72) {
        float v = 0.f;
        #pragma unroll
        for (int ww = 0; ww < 8; ++ww) v += red[ww][tid];
        red[0][tid] = v;
    }
    __syncthreads();
    if (tid < 64) g_o[r * 64 + tid] = red[0][tid] / red[0][64 + (tid >> 3)];
}

// ---------------------------------------------------------------------------
// Kernel C (warp-MMA tf32): per block fixed r, 64 s-rows, 4 warps.
// GEMM1: D1 = x @ GW^T -> sigmoid gate -> ghat (tf32) smem
// GEMM2: D2 = ghat @ Wo -> + bo + exact residual -> out
// ---------------------------------------------------------------------------
__global__ __launch_bounds__(128) void kernelC(
    const float* __restrict__ M, const float* __restrict__ Wg,
    const float* __restrict__ lng, const float* __restrict__ Wo,
    const float* __restrict__ bov, float* __restrict__ outp, int sbase)
{
    extern __shared__ __align__(16) float dyn[];
    float*    XT   = dyn;                          // [64][68] exact x
    float*    GT   = XT + 64 * 68;                 // [64][68] ghat tf32 bits, then D2 f32
    uint32_t* WB1  = (uint32_t*)(GT + 64 * 68);    // [64][72] gate B: [d][j] tf32
    uint32_t* WB2  = WB1 + 64 * 72;                // [64][72] out  B: [j][d] tf32
    float2*   stats = (float2*)(WB2 + 64 * 72);    // [64]
    float*    soo  = (float*)(stats + 64);         // [64]
    float*    sS1g = soo + 64;                     // [64]
    float*    sbG  = sS1g + 64;                    // [64]
    float*    sbo  = sbG + 64;                     // [64]

    const int tid = threadIdx.x, wid = tid >> 5, lid = tid & 31;
    const int g = lid >> 2, tg = lid & 3;
    const int r = blockIdx.y;
    const int s0 = (sbase + blockIdx.x) * 64;

    // weights -> tf32 smem tiles (coalesced gmem reads)
    for (int i = tid; i < 4096; i += 128) {
        int a = i >> 6, b = i & 63;
        WB1[a * 72 + b] = f2tf32(lng[a] * Wg[i]);  // [d][j] = lng[d]*Wg[d][j]
        WB2[a * 72 + b] = f2tf32(Wo[i]);           // [j][d] = Wo[j][d]
    }
    if (tid < 64) {
        soo[tid]  = g_o[r * 64 + tid];
        sS1g[tid] = g_S1g[tid];
        sbG[tid]  = g_bG[tid];
        sbo[tid]  = bov[tid];
        stats[tid] = g_stats[(size_t)r * SS + s0 + tid];
    }
    // x tile (exact f32, coalesced 256B rows)
    #pragma unroll
    for (int it = 0; it < 8; ++it) {
        int f = tid + it * 128;
        int row = f >> 4, c4 = (f & 15) * 4;
        *(float4*)&XT[row * 68 + c4] =
            *(const float4*)&M[(((size_t)(s0 + row)) * RR + r) * 64 + c4];
    }
    __syncthreads();

    const int arow = wid * 16 + g;
    const float2 st0 = stats[arow], st1 = stats[arow + 8];
    uint32_t af[8][4];

    // ---- GEMM1: A = x (cvt tf32 at load) ----
    #pragma unroll
    for (int k = 0; k < 8; ++k) {
        af[k][0] = f2tf32(XT[arow * 68 + k * 8 + tg]);
        af[k][1] = f2tf32(XT[(arow + 8) * 68 + k * 8 + tg]);
        af[k][2] = f2tf32(XT[arow * 68 + k * 8 + tg + 4]);
        af[k][3] = f2tf32(XT[(arow + 8) * 68 + k * 8 + tg + 4]);
    }
    #pragma unroll
    for (int n = 0; n < 8; ++n) {
        float d4[4] = {0.f, 0.f, 0.f, 0.f};
        #pragma unroll
        for (int k = 0; k < 8; ++k) {
            uint32_t b0 = WB1[(k * 8 + tg) * 72 + n * 8 + g];
            uint32_t b1 = WB1[(k * 8 + tg + 4) * 72 + n * 8 + g];
            mma_tf32(d4, af[k], b0, b1);
        }
        const int j0 = n * 8 + 2 * tg;
        const float s1a = sS1g[j0], s1b = sS1g[j0 + 1];
        const float bga = sbG[j0],  bgb = sbG[j0 + 1];
        const float oa  = soo[j0],  ob  = soo[j0 + 1];
        float g00 = oa / (1.f + __expf(-(st0.y * (d4[0] - st0.x * s1a) + bga)));
        float g01 = ob / (1.f + __expf(-(st0.y * (d4[1] - st0.x * s1b) + bgb)));
        float g10 = oa / (1.f + __expf(-(st1.y * (d4[2] - st1.x * s1a) + bga)));
        float g11 = ob / (1.f + __expf(-(st1.y * (d4[3] - st1.x * s1b) + bgb)));
        *(uint2*)&GT[arow * 68 + j0]       = make_uint2(f2tf32(g00), f2tf32(g01));
        *(uint2*)&GT[(arow + 8) * 68 + j0] = make_uint2(f2tf32(g10), f2tf32(g11));
    }
    __syncwarp();

    // ---- GEMM2: A = ghat (already tf32 bits) ----
    {
        const uint32_t* GTu = (const uint32_t*)GT;
        #pragma unroll
        for (int k = 0; k < 8; ++k) {
            af[k][0] = GTu[arow * 68 + k * 8 + tg];
            af[k][1] = GTu[(arow + 8) * 68 + k * 8 + tg];
            af[k][2] = GTu[arow * 68 + k * 8 + tg + 4];
            af[k][3] = GTu[(arow + 8) * 68 + k * 8 + tg + 4];
        }
    }
    __syncwarp();
    #pragma unroll
    for (int n = 0; n < 8; ++n) {
        float d4[4] = {0.f, 0.f, 0.f, 0.f};
        #pragma unroll
        for (int k = 0; k < 8; ++k) {
            uint32_t b0 = WB2[(k * 8 + tg) * 72 + n * 8 + g];
            uint32_t b1 = WB2[(k * 8 + tg + 4) * 72 + n * 8 + g];
            mma_tf32(d4, af[k], b0, b1);
        }
        const int c0 = n * 8 + 2 * tg;
        *(float2*)&GT[arow * 68 + c0]       = make_float2(d4[0], d4[1]);
        *(float2*)&GT[(arow + 8) * 68 + c0] = make_float2(d4[2], d4[3]);
    }
    __syncwarp();

    // ---- epilogue: out = D2 + bo + x (exact residual); warp owns its rows ----
    #pragma unroll
    for (int it = 0; it < 8; ++it) {
        int f = lid + it * 32;
        int row = wid * 16 + (f >> 4), c4 = (f & 15) * 4;
        float4 dv = *(const float4*)&GT[row * 68 + c4];
        float4 xv = *(const float4*)&XT[row * 68 + c4];
        float4 ov;
        ov.x = dv.x + sbo[c4 + 0] + xv.x;
        ov.y = dv.y + sbo[c4 + 1] + xv.y;
        ov.z = dv.z + sbo[c4 + 2] + xv.z;
        ov.w = dv.w + sbo[c4 + 3] + xv.w;
        *(float4*)&outp[(((size_t)(s0 + row)) * RR + r) * 64 + c4] = ov;
    }
}

// ---------------------------------------------------------------------------
extern "C" void kernel_launch(void* const* d_in, const int* in_sizes, int n_in,
                              void* d_out, int out_size)
{
    (void)in_sizes; (void)n_in; (void)out_size;
    const float* M    = (const float*)d_in[0];
    const float* mask = (const float*)d_in[1];
    const float* ln_g = (const float*)d_in[2];
    const float* ln_b = (const float*)d_in[3];
    const float* Wq   = (const float*)d_in[4];
    const float* Wk   = (const float*)d_in[5];
    const float* Wv   = (const float*)d_in[6];
    const float* Wg   = (const float*)d_in[7];
    const float* bg   = (const float*)d_in[8];
    const float* Wo   = (const float*)d_in[9];
    const float* bo   = (const float*)d_in[10];
    float* outp = (float*)d_out;

    // smem: XT+GT (2*64*68*4) + WB1+WB2 (2*64*72*4) + stats(512) + 4*256
    const int smemC = 2 * 64 * 68 * 4 + 2 * 64 * 72 * 4 + 512 + 4 * 256;  // 73216
    cudaFuncSetAttribute(kernelC, cudaFuncAttributeMaxDynamicSharedMemorySize, smemC);

    kernelDP<<<769, 256>>>(mask, ln_g, ln_b, Wk, Wv, Wg, bg, Wo);
    kernelA<<<dim3(16, 384), 128>>>(M);
    kernelB<<<384, 256>>>(Wq, ln_g, ln_b);
    kernelC<<<dim3(11, 384), 128, smemC>>>(M, Wg, ln_g, Wo, bo, outp, 0);
    kernelC<<<dim3(11, 384), 128, smemC>>>(M, Wg, ln_g, Wo, bo, outp, 11);
    kernelC<<<dim3(10, 384), 128, smemC>>>(M, Wg, ln_g, Wo, bo, outp, 22);
}

// round 13
// speedup vs baseline: 2.1027x; 1.1136x over previous
#include <cuda_runtime.h>
#include <cstdint>

#define SS 2048
#define RR 384

typedef unsigned long long ull;

// ---- device scratch (no allocs allowed) ----
__device__ float g_kv[RR * 16 * SS];     // [r][c][s]; c: 0-7 = k, 8-15 = v
__device__ float g_maskT[RR * SS];       // transposed mask [r][s]
__device__ float g_qpart[RR * 16 * 68];  // per-(r, s-block) partials
__device__ float g_o[RR * 64];           // attention output per r  [h*8+c]
__device__ float2 g_stats[RR * SS];      // per-row (mu, rstd), [r][s] layout
// LN-folded weights
__device__ float g_AW[16 * 64];          // [c][d] = g[d]*Wkv[d][c]
__device__ float g_S1kv[16];
__device__ float g_bkv[16];
__device__ float g_GW[64 * 64];          // [j][d] = g[d]*Wg[d][j]
__device__ float g_S1g[64];
__device__ float g_bG[64];               // bg[j] + sum_d b[d]*Wg[d][j]
__device__ float g_WoT[64 * 64];         // [d][j] = Wo[j][d]
// pre-packed tf32 B-fragments for kernelC  (chunk c holds k-steps 2c, 2c+1)
__device__ uint4 g_BP1[1024];            // gate GEMM:  [c][n*32+lane]
__device__ uint4 g_BP2[1024];            // out  GEMM:  [c][n*32+lane]

// ---- packed fp32x2 helpers ----
__device__ __forceinline__ ull ffma2(ull a, ull b, ull c) {
    ull d;
    asm("fma.rn.f32x2 %0, %1, %2, %3;" : "=l"(d) : "l"(a), "l"(b), "l"(c));
    return d;
}
__device__ __forceinline__ float2 upk(ull v) {
    float2 f; asm("mov.b64 {%0,%1}, %2;" : "=f"(f.x), "=f"(f.y) : "l"(v)); return f;
}
__device__ __forceinline__ ull pk2(float lo, float hi) {
    ull r; asm("mov.b64 %0, {%1,%2};" : "=l"(r) : "f"(lo), "f"(hi)); return r;
}

// ---- warp MMA helpers (arch-legal on compute_103) ----
__device__ __forceinline__ uint32_t f2tf32(float x) {
    uint32_t r; asm("cvt.rna.tf32.f32 %0, %1;" : "=r"(r) : "f"(x)); return r;
}
__device__ __forceinline__ void mma_tf32(float* d, const uint32_t* a,
                                         uint32_t b0, uint32_t b1) {
    asm volatile(
        "mma.sync.aligned.m16n8k8.row.col.f32.tf32.tf32.f32 "
        "{%0,%1,%2,%3}, {%4,%5,%6,%7}, {%8,%9}, {%0,%1,%2,%3};"
        : "+f"(d[0]), "+f"(d[1]), "+f"(d[2]), "+f"(d[3])
        : "r"(a[0]), "r"(a[1]), "r"(a[2]), "r"(a[3]), "r"(b0), "r"(b1));
}

// ---------------------------------------------------------------------------
// Kernel DP: mask transpose (blocks 0..767) + weight folding/packing (768)
// ---------------------------------------------------------------------------
__global__ __launch_bounds__(256) void kernelDP(
    const float* __restrict__ Mmask,
    const float* __restrict__ lng, const float* __restrict__ lnb,
    const float* __restrict__ Wk, const float* __restrict__ Wv,
    const float* __restrict__ Wg, const float* __restrict__ bg,
    const float* __restrict__ Wo)
{
    const int tid = threadIdx.x;
    if (blockIdx.x < 768) {
        __shared__ float t[32][33];
        const int bx = blockIdx.x % 12, by = blockIdx.x / 12;
        const int tx = tid & 31, ty = tid >> 5;
        const int r0 = bx * 32, s0 = by * 32;
        #pragma unroll
        for (int k = 0; k < 32; k += 8)
            t[ty + k][tx] = Mmask[(s0 + ty + k) * RR + r0 + tx];
        __syncthreads();
        #pragma unroll
        for (int k = 0; k < 32; k += 8)
            g_maskT[(r0 + ty + k) * SS + s0 + tx] = t[tx][ty + k];
    } else {
        for (int i = tid; i < 16 * 64; i += 256) {
            int c = i >> 6, d = i & 63;
            float w = (c < 8) ? Wk[d * 8 + c] : Wv[d * 8 + c - 8];
            g_AW[i] = lng[d] * w;
        }
        for (int i = tid; i < 64 * 64; i += 256) {
            int a = i >> 6, b = i & 63;
            g_GW[i]  = lng[b] * Wg[b * 64 + a];   // [j=a][d=b]
            g_WoT[i] = Wo[b * 64 + a];            // [d=a][j=b]
        }
        // pre-packed tf32 B fragments for kernelC
        for (int i = tid; i < 1024; i += 256) {
            int c = i >> 8, rem = i & 255;
            int col = rem >> 2, tg = rem & 3;
            int d0 = 16 * c + tg, d1 = d0 + 4, d2 = d0 + 8, d3 = d0 + 12;
            uint4 v1, v2;
            v1.x = f2tf32(lng[d0] * Wg[d0 * 64 + col]);
            v1.y = f2tf32(lng[d1] * Wg[d1 * 64 + col]);
            v1.z = f2tf32(lng[d2] * Wg[d2 * 64 + col]);
            v1.w = f2tf32(lng[d3] * Wg[d3 * 64 + col]);
            g_BP1[i] = v1;
            v2.x = f2tf32(Wo[d0 * 64 + col]);
            v2.y = f2tf32(Wo[d1 * 64 + col]);
            v2.z = f2tf32(Wo[d2 * 64 + col]);
            v2.w = f2tf32(Wo[d3 * 64 + col]);
            g_BP2[i] = v2;
        }
        __syncthreads();
        if (tid < 16) {
            float s1 = 0.f, bb = 0.f;
            for (int d = 0; d < 64; ++d) {
                s1 += g_AW[tid * 64 + d];
                float w = (tid < 8) ? Wk[d * 8 + tid] : Wv[d * 8 + tid - 8];
                bb += lnb[d] * w;
            }
            g_S1kv[tid] = s1; g_bkv[tid] = bb;
        }
        if (tid >= 64 && tid < 128) {
            int j = tid - 64;
            float s1 = 0.f, bb = 0.f;
            for (int d = 0; d < 64; ++d) {
                s1 += g_GW[j * 64 + d];
                bb += lnb[d] * Wg[d * 64 + j];
            }
            g_S1g[j] = s1; g_bG[j] = bg[j] + bb;
        }
    }
}

// ---------------------------------------------------------------------------
// Kernel A: rows-in-lanes LN (folded) + k/v projection + masked-q partials
// + stores per-row (mu, rstd) to g_stats[r][s] for kernelC
// ---------------------------------------------------------------------------
__global__ __launch_bounds__(128) void kernelA(const float* __restrict__ M) {
    __shared__ __align__(16) float stage[4][32][68];
    __shared__ __align__(16) float sAW[16][68];
    __shared__ float sS1[16], sbk[16];
    __shared__ float sQ[4][68];
    const int tid = threadIdx.x, w = tid >> 5, t = tid & 31;
    const int r = blockIdx.y;
    const int srow = blockIdx.x * 128 + w * 32;

    for (int i = tid; i < 16 * 64; i += 128) { int c = i >> 6, d = i & 63; sAW[c][d] = g_AW[i]; }
    if (tid < 16) { sS1[tid] = g_S1kv[tid]; sbk[tid] = g_bkv[tid]; }
    __syncthreads();

    const int cr = t >> 4, cc = (t & 15) * 4;
    #pragma unroll
    for (int i = 0; i < 16; ++i) {
        int rr = i * 2 + cr;
        *(float4*)&stage[w][rr][cc] =
            *(const float4*)&M[(((srow + rr) * RR) + r) * 64 + cc];
    }
    __syncwarp();

    ull xp[32];
    {
        const ulonglong2* rp = (const ulonglong2*)&stage[w][t][0];
        #pragma unroll
        for (int i = 0; i < 16; ++i) { ulonglong2 v = rp[i]; xp[2 * i] = v.x; xp[2 * i + 1] = v.y; }
    }
    float sum = 0.f, sq = 0.f;
    #pragma unroll
    for (int i = 0; i < 32; ++i) { float2 f = upk(xp[i]); sum += f.x + f.y; sq += f.x * f.x + f.y * f.y; }
    const float mu = sum * (1.f / 64.f);
    const float rstd = rsqrtf(sq * (1.f / 64.f) - mu * mu + 1e-5f);
    const int s = srow + t;
    const float mk = g_maskT[r * SS + s];
    g_stats[(size_t)r * SS + s] = make_float2(mu, rstd);

    #pragma unroll
    for (int c = 0; c < 16; ++c) {
        const ulonglong2* wp_ = (const ulonglong2*)&sAW[c][0];
        ull a0 = 0ull, a1 = 0ull;
        #pragma unroll
        for (int i = 0; i < 16; ++i) {
            ulonglong2 v = wp_[i];
            a0 = ffma2(xp[2 * i], v.x, a0);
            a1 = ffma2(xp[2 * i + 1], v.y, a1);
        }
        float2 f0 = upk(a0), f1 = upk(a1);
        float dot = f0.x + f0.y + f1.x + f1.y;
        g_kv[((r * 16 + c) * SS) + s] = rstd * (dot - mu * sS1[c]) + sbk[c];
    }

    {
        const float mkr = mk * rstd;
        const ull mp = pk2(mkr, mkr);
        float4* qr = (float4*)&stage[w][t][0];
        #pragma unroll
        for (int i = 0; i < 16; ++i) {
            float2 a = upk(ffma2(xp[2 * i], mp, 0ull));
            float2 b = upk(ffma2(xp[2 * i + 1], mp, 0ull));
            qr[i] = make_float4(a.x, a.y, b.x, b.y);
        }
        stage[w][t][64] = mkr * mu;
        stage[w][t][65] = mk;
    }
    __syncwarp();
    {
        float ax = 0.f, ay = 0.f;
        #pragma unroll
        for (int rr = 0; rr < 32; ++rr) {
            float2 v = *(const float2*)&stage[w][rr][2 * t];
            ax += v.x; ay += v.y;
        }
        sQ[w][2 * t] = ax; sQ[w][2 * t + 1] = ay;
        if (t < 2) {
            float e = 0.f;
            #pragma unroll
            for (int rr = 0; rr < 32; ++rr) e += stage[w][rr][64 + t];
            sQ[w][64 + t] = e;
        }
    }
    __syncthreads();
    if (tid < 66) {
        float a = sQ[0][tid] + sQ[1][tid] + sQ[2][tid] + sQ[3][tid];
        g_qpart[(r * 16 + blockIdx.x) * 68 + tid] = a;
    }
}

// ---------------------------------------------------------------------------
// Kernel B: pooled q, two-pass streaming softmax over S (52us version)
// ---------------------------------------------------------------------------
__global__ __launch_bounds__(256) void kernelB(
    const float* __restrict__ Wq, const float* __restrict__ lng,
    const float* __restrict__ lnb)
{
    __shared__ float sqa[68];
    __shared__ float sq[64];
    __shared__ float smax[8];
    __shared__ float red[8][80];
    const int tid = threadIdx.x, w = tid >> 5, t = tid & 31, r = blockIdx.x;

    if (tid < 66) {
        float a = 0.f;
        #pragma unroll
        for (int c = 0; c < 16; ++c) a += g_qpart[(r * 16 + c) * 68 + tid];
        sqa[tid] = a;
    }
    __syncthreads();
    if (tid < 64) {
        float Pmu = sqa[64], Pc = sqa[65];
        sqa[tid] = (lng[tid] * (sqa[tid] - Pmu) + lnb[tid] * Pc) / (Pc + 1e-10f);
    }
    __syncthreads();
    if (tid < 64) {
        float acc = 0.f;
        #pragma unroll
        for (int d = 0; d < 64; ++d) acc += sqa[d] * Wq[d * 64 + tid];
        sq[tid] = acc * 0.35355339059327373f;
    }
    __syncthreads();

    float mx[8];
    #pragma unroll
    for (int h = 0; h < 8; ++h) mx[h] = -3.0e38f;
    for (int s = tid; s < SS; s += 256) {
        float kk[8];
        #pragma unroll
        for (int c = 0; c < 8; ++c) kk[c] = g_kv[((r * 16 + c) * SS) + s];
        float bias = 1e9f * (g_maskT[r * SS + s] - 1.f);
        #pragma unroll
        for (int h = 0; h < 8; ++h) {
            float lg = bias;
            #pragma unroll
            for (int c = 0; c < 8; ++c) lg += sq[h * 8 + c] * kk[c];
            mx[h] = fmaxf(mx[h], lg);
        }
    }
    #pragma unroll
    for (int h = 0; h < 8; ++h) {
        #pragma unroll
        for (int o = 16; o > 0; o >>= 1) mx[h] = fmaxf(mx[h], __shfl_xor_sync(0xffffffffu, mx[h], o));
    }
    if (t < 8) red[w][t] = mx[t];
    __syncthreads();
    if (tid < 8) {
        float m = red[0][tid];
        #pragma unroll
        for (int ww = 1; ww < 8; ++ww) m = fmaxf(m, red[ww][tid]);
        smax[tid] = m;
    }
    __syncthreads();

    float Z[8];
    float acc[64];
    #pragma unroll
    for (int h = 0; h < 8; ++h) Z[h] = 0.f;
    #pragma unroll
    for (int i = 0; i < 64; ++i) acc[i] = 0.f;
    for (int s = tid; s < SS; s += 256) {
        float kk[8], vv[8];
        #pragma unroll
        for (int c = 0; c < 8; ++c) kk[c] = g_kv[((r * 16 + c) * SS) + s];
        #pragma unroll
        for (int c = 0; c < 8; ++c) vv[c] = g_kv[((r * 16 + 8 + c) * SS) + s];
        float bias = 1e9f * (g_maskT[r * SS + s] - 1.f);
        #pragma unroll
        for (int h = 0; h < 8; ++h) {
            float lg = bias;
            #pragma unroll
            for (int c = 0; c < 8; ++c) lg += sq[h * 8 + c] * kk[c];
            float e = __expf(lg - smax[h]);
            Z[h] += e;
            #pragma unroll
            for (int c = 0; c < 8; ++c) acc[h * 8 + c] += e * vv[c];
        }
    }
    #pragma unroll
    for (int i = 0; i < 64; ++i) {
        float v = acc[i];
        #pragma unroll
        for (int o = 16; o > 0; o >>= 1) v += __shfl_xor_sync(0xffffffffu, v, o);
        if (t == 0) red[w][i] = v;
    }
    #pragma unroll
    for (int h = 0; h < 8; ++h) {
        float v = Z[h];
        #pragma unroll
        for (int o = 16; o > 0; o >>= 1) v += __shfl_xor_sync(0xffffffffu, v, o);
        if (t == 0) red[w][64 + h] = v;
    }
    __syncthreads();
    if (tid < 72) {
        float v = 0.f;
        #pragma unroll
        for (int ww = 0; ww < 8; ++ww) v += red[ww][tid];
        red[0][tid] = v;
    }
    __syncthreads();
    if (tid < 64) g_o[r * 64 + tid] = red[0][tid] / red[0][64 + (tid >> 3)];
}

// ---------------------------------------------------------------------------
// Kernel C (warp-MMA tf32, v2): block = fixed r, 4 tiles of 64 s-rows.
// Pre-packed B frags via LDS.128; warp-synchronous mainloop (no block barriers)
// ---------------------------------------------------------------------------
__global__ __launch_bounds__(128) void kernelC(
    const float* __restrict__ M, const float* __restrict__ bov,
    float* __restrict__ outp, int sbase)
{
    extern __shared__ __align__(16) float dyn[];
    float* XT   = dyn;                         // [64][68] exact x
    float* GT   = XT + 64 * 68;                // [64][68] ghat bits / out
    uint4* BP1s = (uint4*)(GT + 64 * 68);      // [1024] gate B frags
    uint4* BP2s = BP1s + 1024;                 // [1024] out  B frags
    float* soo  = (float*)(BP2s + 1024);       // [64]
    float* sS1g = soo + 64;                    // [64]
    float* sbG  = sS1g + 64;                   // [64]
    float* sbo  = sbG + 64;                    // [64]

    const int tid = threadIdx.x, wid = tid >> 5, lid = tid & 31;
    const int g = lid >> 2, tg = lid & 3;
    const int r = blockIdx.y;
    const int xb = sbase + blockIdx.x;

    for (int i = tid; i < 1024; i += 128) { BP1s[i] = g_BP1[i]; BP2s[i] = g_BP2[i]; }
    if (tid < 64) {
        soo[tid]  = g_o[r * 64 + tid];
        sS1g[tid] = g_S1g[tid];
        sbG[tid]  = g_bG[tid];
        sbo[tid]  = bov[tid];
    }
    __syncthreads();

    const int arow = wid * 16 + g;

    for (int t = 0; t < 4; ++t) {
        const int s0 = (xb * 4 + t) * 64;
        // warp-local tile load (warp owns rows [wid*16, wid*16+16))
        #pragma unroll
        for (int it = 0; it < 8; ++it) {
            int f = lid + it * 32;
            int row = wid * 16 + (f >> 4), c4 = (f & 15) * 4;
            *(float4*)&XT[row * 68 + c4] =
                *(const float4*)&M[(((size_t)(s0 + row)) * RR + r) * 64 + c4];
        }
        __syncwarp();

        const float2 st0 = g_stats[(size_t)r * SS + s0 + arow];
        const float2 st1 = g_stats[(size_t)r * SS + s0 + arow + 8];

        uint32_t af[8][4];
        #pragma unroll
        for (int k = 0; k < 8; ++k) {
            af[k][0] = f2tf32(XT[arow * 68 + k * 8 + tg]);
            af[k][1] = f2tf32(XT[(arow + 8) * 68 + k * 8 + tg]);
            af[k][2] = f2tf32(XT[arow * 68 + k * 8 + tg + 4]);
            af[k][3] = f2tf32(XT[(arow + 8) * 68 + k * 8 + tg + 4]);
        }
        // ---- GEMM1 + sigmoid gate epilogue ----
        #pragma unroll
        for (int n = 0; n < 8; ++n) {
            float d4[4] = {0.f, 0.f, 0.f, 0.f};
            uint4 q0 = BP1s[n * 32 + lid];
            uint4 q1 = BP1s[256 + n * 32 + lid];
            uint4 q2 = BP1s[512 + n * 32 + lid];
            uint4 q3 = BP1s[768 + n * 32 + lid];
            mma_tf32(d4, af[0], q0.x, q0.y); mma_tf32(d4, af[1], q0.z, q0.w);
            mma_tf32(d4, af[2], q1.x, q1.y); mma_tf32(d4, af[3], q1.z, q1.w);
            mma_tf32(d4, af[4], q2.x, q2.y); mma_tf32(d4, af[5], q2.z, q2.w);
            mma_tf32(d4, af[6], q3.x, q3.y); mma_tf32(d4, af[7], q3.z, q3.w);
            const int j0 = n * 8 + 2 * tg;
            const float s1a = sS1g[j0], s1b = sS1g[j0 + 1];
            const float bga = sbG[j0],  bgb = sbG[j0 + 1];
            const float oa  = soo[j0],  ob  = soo[j0 + 1];
            float g00 = oa / (1.f + __expf(-(st0.y * (d4[0] - st0.x * s1a) + bga)));
            float g01 = ob / (1.f + __expf(-(st0.y * (d4[1] - st0.x * s1b) + bgb)));
            float g10 = oa / (1.f + __expf(-(st1.y * (d4[2] - st1.x * s1a) + bga)));
            float g11 = ob / (1.f + __expf(-(st1.y * (d4[3] - st1.x * s1b) + bgb)));
            *(uint2*)&GT[arow * 68 + j0]       = make_uint2(f2tf32(g00), f2tf32(g01));
            *(uint2*)&GT[(arow + 8) * 68 + j0] = make_uint2(f2tf32(g10), f2tf32(g11));
        }
        __syncwarp();

        // ---- GEMM2 A frags (ghat, already tf32 bits) ----
        {
            const uint32_t* GTu = (const uint32_t*)GT;
            #pragma unroll
            for (int k = 0; k < 8; ++k) {
                af[k][0] = GTu[arow * 68 + k * 8 + tg];
                af[k][1] = GTu[(arow + 8) * 68 + k * 8 + tg];
                af[k][2] = GTu[arow * 68 + k * 8 + tg + 4];
                af[k][3] = GTu[(arow + 8) * 68 + k * 8 + tg + 4];
            }
        }
        __syncwarp();
        // ---- GEMM2 + bias + exact residual -> GT (as f32) ----
        #pragma unroll
        for (int n = 0; n < 8; ++n) {
            float d4[4] = {0.f, 0.f, 0.f, 0.f};
            uint4 q0 = BP2s[n * 32 + lid];
            uint4 q1 = BP2s[256 + n * 32 + lid];
            uint4 q2 = BP2s[512 + n * 32 + lid];
            uint4 q3 = BP2s[768 + n * 32 + lid];
            mma_tf32(d4, af[0], q0.x, q0.y); mma_tf32(d4, af[1], q0.z, q0.w);
            mma_tf32(d4, af[2], q1.x, q1.y); mma_tf32(d4, af[3], q1.z, q1.w);
            mma_tf32(d4, af[4], q2.x, q2.y); mma_tf32(d4, af[5], q2.z, q2.w);
            mma_tf32(d4, af[6], q3.x, q3.y); mma_tf32(d4, af[7], q3.z, q3.w);
            const int c0 = n * 8 + 2 * tg;
            float2 x0 = *(const float2*)&XT[arow * 68 + c0];
            float2 x1 = *(const float2*)&XT[(arow + 8) * 68 + c0];
            *(float2*)&GT[arow * 68 + c0] =
                make_float2(d4[0] + sbo[c0] + x0.x, d4[1] + sbo[c0 + 1] + x0.y);
            *(float2*)&GT[(arow + 8) * 68 + c0] =
                make_float2(d4[2] + sbo[c0] + x1.x, d4[3] + sbo[c0 + 1] + x1.y);
        }
        __syncwarp();

        // warp-local coalesced store
        #pragma unroll
        for (int it = 0; it < 8; ++it) {
            int f = lid + it * 32;
            int row = wid * 16 + (f >> 4), c4 = (f & 15) * 4;
            *(float4*)&outp[(((size_t)(s0 + row)) * RR + r) * 64 + c4] =
                *(const float4*)&GT[row * 68 + c4];
        }
        __syncwarp();
    }
}

// ---------------------------------------------------------------------------
extern "C" void kernel_launch(void* const* d_in, const int* in_sizes, int n_in,
                              void* d_out, int out_size)
{
    (void)in_sizes; (void)n_in; (void)out_size;
    const float* M    = (const float*)d_in[0];
    const float* mask = (const float*)d_in[1];
    const float* ln_g = (const float*)d_in[2];
    const float* ln_b = (const float*)d_in[3];
    const float* Wq   = (const float*)d_in[4];
    const float* Wk   = (const float*)d_in[5];
    const float* Wv   = (const float*)d_in[6];
    const float* Wg   = (const float*)d_in[7];
    const float* bg   = (const float*)d_in[8];
    const float* Wo   = (const float*)d_in[9];
    const float* bo   = (const float*)d_in[10];
    float* outp = (float*)d_out;

    // smem: XT+GT (2*64*68*4=34816) + BP1+BP2 (2*16384) + 4*256 = 68352 B
    const int smemC = 2 * 64 * 68 * 4 + 2 * 16384 + 4 * 256;
    cudaFuncSetAttribute(kernelC, cudaFuncAttributeMaxDynamicSharedMemorySize, smemC);

    kernelDP<<<769, 256>>>(mask, ln_g, ln_b, Wk, Wv, Wg, bg, Wo);
    kernelA<<<dim3(16, 384), 128>>>(M);
    kernelB<<<384, 256>>>(Wq, ln_g, ln_b);
    kernelC<<<dim3(3, 384), 128, smemC>>>(M, bo, outp, 0);
    kernelC<<<dim3(3, 384), 128, smemC>>>(M, bo, outp, 3);
    kernelC<<<dim3(2, 384), 128, smemC>>>(M, bo, outp, 6);
}

// round 14
// speedup vs baseline: 2.1994x; 1.0460x over previous
#include <cuda_runtime.h>
#include <cstdint>

#define SS 2048
#define RR 384

typedef unsigned long long ull;

// ---- device scratch (no allocs allowed) ----
__device__ float g_kv[RR * 16 * SS];     // [r][c][s]; c: 0-7 = k, 8-15 = v
__device__ float g_maskT[RR * SS];       // transposed mask [r][s]
__device__ float g_qpart[RR * 16 * 68];  // per-(r, s-block) partials
__device__ float g_o[RR * 64];           // attention output per r  [h*8+c]
__device__ float2 g_stats[RR * SS];      // per-row (mu, rstd), [r][s] layout
// LN-folded weights
__device__ float g_AW[16 * 64];          // [c][d] = g[d]*Wkv[d][c]
__device__ float g_S1kv[16];
__device__ float g_bkv[16];
__device__ float g_GW[64 * 64];          // [j][d] = g[d]*Wg[d][j]
__device__ float g_S1g[64];
__device__ float g_bG[64];               // bg[j] + sum_d b[d]*Wg[d][j]
__device__ float g_WoT[64 * 64];         // [d][j] = Wo[j][d]
// pre-packed tf32 B-fragments for kernelC  (chunk c holds k-steps 2c, 2c+1)
__device__ uint4 g_BP1[1024];            // gate GEMM:  [c][n*32+lane]
__device__ uint4 g_BP2[1024];            // out  GEMM:  [c][n*32+lane]

// ---- packed fp32x2 helpers ----
__device__ __forceinline__ ull ffma2(ull a, ull b, ull c) {
    ull d;
    asm("fma.rn.f32x2 %0, %1, %2, %3;" : "=l"(d) : "l"(a), "l"(b), "l"(c));
    return d;
}
__device__ __forceinline__ float2 upk(ull v) {
    float2 f; asm("mov.b64 {%0,%1}, %2;" : "=f"(f.x), "=f"(f.y) : "l"(v)); return f;
}
__device__ __forceinline__ ull pk2(float lo, float hi) {
    ull r; asm("mov.b64 %0, {%1,%2};" : "=l"(r) : "f"(lo), "f"(hi)); return r;
}

// ---- warp MMA helpers (arch-legal on compute_103) ----
__device__ __forceinline__ uint32_t f2tf32(float x) {
    uint32_t r; asm("cvt.rna.tf32.f32 %0, %1;" : "=r"(r) : "f"(x)); return r;
}
__device__ __forceinline__ void mma_tf32(float* d, const uint32_t* a,
                                         uint32_t b0, uint32_t b1) {
    asm volatile(
        "mma.sync.aligned.m16n8k8.row.col.f32.tf32.tf32.f32 "
        "{%0,%1,%2,%3}, {%4,%5,%6,%7}, {%8,%9}, {%0,%1,%2,%3};"
        : "+f"(d[0]), "+f"(d[1]), "+f"(d[2]), "+f"(d[3])
        : "r"(a[0]), "r"(a[1]), "r"(a[2]), "r"(a[3]), "r"(b0), "r"(b1));
}

// ---------------------------------------------------------------------------
// Kernel DP: mask transpose (blocks 0..767) + weight folding/packing (768)
// ---------------------------------------------------------------------------
__global__ __launch_bounds__(256) void kernelDP(
    const float* __restrict__ Mmask,
    const float* __restrict__ lng, const float* __restrict__ lnb,
    const float* __restrict__ Wk, const float* __restrict__ Wv,
    const float* __restrict__ Wg, const float* __restrict__ bg,
    const float* __restrict__ Wo)
{
    const int tid = threadIdx.x;
    if (blockIdx.x < 768) {
        __shared__ float t[32][33];
        const int bx = blockIdx.x % 12, by = blockIdx.x / 12;
        const int tx = tid & 31, ty = tid >> 5;
        const int r0 = bx * 32, s0 = by * 32;
        #pragma unroll
        for (int k = 0; k < 32; k += 8)
            t[ty + k][tx] = Mmask[(s0 + ty + k) * RR + r0 + tx];
        __syncthreads();
        #pragma unroll
        for (int k = 0; k < 32; k += 8)
            g_maskT[(r0 + ty + k) * SS + s0 + tx] = t[tx][ty + k];
    } else {
        for (int i = tid; i < 16 * 64; i += 256) {
            int c = i >> 6, d = i & 63;
            float w = (c < 8) ? Wk[d * 8 + c] : Wv[d * 8 + c - 8];
            g_AW[i] = lng[d] * w;
        }
        for (int i = tid; i < 64 * 64; i += 256) {
            int a = i >> 6, b = i & 63;
            g_GW[i]  = lng[b] * Wg[b * 64 + a];   // [j=a][d=b]
            g_WoT[i] = Wo[b * 64 + a];            // [d=a][j=b]
        }
        // pre-packed tf32 B fragments for kernelC
        for (int i = tid; i < 1024; i += 256) {
            int c = i >> 8, rem = i & 255;
            int col = rem >> 2, tg = rem & 3;
            int d0 = 16 * c + tg, d1 = d0 + 4, d2 = d0 + 8, d3 = d0 + 12;
            uint4 v1, v2;
            v1.x = f2tf32(lng[d0] * Wg[d0 * 64 + col]);
            v1.y = f2tf32(lng[d1] * Wg[d1 * 64 + col]);
            v1.z = f2tf32(lng[d2] * Wg[d2 * 64 + col]);
            v1.w = f2tf32(lng[d3] * Wg[d3 * 64 + col]);
            g_BP1[i] = v1;
            v2.x = f2tf32(Wo[d0 * 64 + col]);
            v2.y = f2tf32(Wo[d1 * 64 + col]);
            v2.z = f2tf32(Wo[d2 * 64 + col]);
            v2.w = f2tf32(Wo[d3 * 64 + col]);
            g_BP2[i] = v2;
        }
        __syncthreads();
        if (tid < 16) {
            float s1 = 0.f, bb = 0.f;
            for (int d = 0; d < 64; ++d) {
                s1 += g_AW[tid * 64 + d];
                float w = (tid < 8) ? Wk[d * 8 + tid] : Wv[d * 8 + tid - 8];
                bb += lnb[d] * w;
            }
            g_S1kv[tid] = s1; g_bkv[tid] = bb;
        }
        if (tid >= 64 && tid < 128) {
            int j = tid - 64;
            float s1 = 0.f, bb = 0.f;
            for (int d = 0; d < 64; ++d) {
                s1 += g_GW[j * 64 + d];
                bb += lnb[d] * Wg[d * 64 + j];
            }
            g_S1g[j] = s1; g_bG[j] = bg[j] + bb;
        }
    }
}

// ---------------------------------------------------------------------------
// Kernel A: rows-in-lanes LN (folded) + k/v projection + masked-q partials
// + stores per-row (mu, rstd) to g_stats[r][s] for kernelC
// ---------------------------------------------------------------------------
__global__ __launch_bounds__(128) void kernelA(const float* __restrict__ M) {
    __shared__ __align__(16) float stage[4][32][68];
    __shared__ __align__(16) float sAW[16][68];
    __shared__ float sS1[16], sbk[16];
    __shared__ float sQ[4][68];
    const int tid = threadIdx.x, w = tid >> 5, t = tid & 31;
    const int r = blockIdx.y;
    const int srow = blockIdx.x * 128 + w * 32;

    for (int i = tid; i < 16 * 64; i += 128) { int c = i >> 6, d = i & 63; sAW[c][d] = g_AW[i]; }
    if (tid < 16) { sS1[tid] = g_S1kv[tid]; sbk[tid] = g_bkv[tid]; }
    __syncthreads();

    const int cr = t >> 4, cc = (t & 15) * 4;
    #pragma unroll
    for (int i = 0; i < 16; ++i) {
        int rr = i * 2 + cr;
        *(float4*)&stage[w][rr][cc] =
            *(const float4*)&M[(((srow + rr) * RR) + r) * 64 + cc];
    }
    __syncwarp();

    ull xp[32];
    {
        const ulonglong2* rp = (const ulonglong2*)&stage[w][t][0];
        #pragma unroll
        for (int i = 0; i < 16; ++i) { ulonglong2 v = rp[i]; xp[2 * i] = v.x; xp[2 * i + 1] = v.y; }
    }
    float sum = 0.f, sq = 0.f;
    #pragma unroll
    for (int i = 0; i < 32; ++i) { float2 f = upk(xp[i]); sum += f.x + f.y; sq += f.x * f.x + f.y * f.y; }
    const float mu = sum * (1.f / 64.f);
    const float rstd = rsqrtf(sq * (1.f / 64.f) - mu * mu + 1e-5f);
    const int s = srow + t;
    const float mk = g_maskT[r * SS + s];
    g_stats[(size_t)r * SS + s] = make_float2(mu, rstd);

    #pragma unroll
    for (int c = 0; c < 16; ++c) {
        const ulonglong2* wp_ = (const ulonglong2*)&sAW[c][0];
        ull a0 = 0ull, a1 = 0ull;
        #pragma unroll
        for (int i = 0; i < 16; ++i) {
            ulonglong2 v = wp_[i];
            a0 = ffma2(xp[2 * i], v.x, a0);
            a1 = ffma2(xp[2 * i + 1], v.y, a1);
        }
        float2 f0 = upk(a0), f1 = upk(a1);
        float dot = f0.x + f0.y + f1.x + f1.y;
        g_kv[((r * 16 + c) * SS) + s] = rstd * (dot - mu * sS1[c]) + sbk[c];
    }

    {
        const float mkr = mk * rstd;
        const ull mp = pk2(mkr, mkr);
        float4* qr = (float4*)&stage[w][t][0];
        #pragma unroll
        for (int i = 0; i < 16; ++i) {
            float2 a = upk(ffma2(xp[2 * i], mp, 0ull));
            float2 b = upk(ffma2(xp[2 * i + 1], mp, 0ull));
            qr[i] = make_float4(a.x, a.y, b.x, b.y);
        }
        stage[w][t][64] = mkr * mu;
        stage[w][t][65] = mk;
    }
    __syncwarp();
    {
        float ax = 0.f, ay = 0.f;
        #pragma unroll
        for (int rr = 0; rr < 32; ++rr) {
            float2 v = *(const float2*)&stage[w][rr][2 * t];
            ax += v.x; ay += v.y;
        }
        sQ[w][2 * t] = ax; sQ[w][2 * t + 1] = ay;
        if (t < 2) {
            float e = 0.f;
            #pragma unroll
            for (int rr = 0; rr < 32; ++rr) e += stage[w][rr][64 + t];
            sQ[w][64 + t] = e;
        }
    }
    __syncthreads();
    if (tid < 66) {
        float a = sQ[0][tid] + sQ[1][tid] + sQ[2][tid] + sQ[3][tid];
        g_qpart[(r * 16 + blockIdx.x) * 68 + tid] = a;
    }
}

// ---------------------------------------------------------------------------
// Kernel B: pooled q, two-pass streaming softmax over S (52us version)
// ---------------------------------------------------------------------------
__global__ __launch_bounds__(256) void kernelB(
    const float* __restrict__ Wq, const float* __restrict__ lng,
    const float* __restrict__ lnb)
{
    __shared__ float sqa[68];
    __shared__ float sq[64];
    __shared__ float smax[8];
    __shared__ float red[8][80];
    const int tid = threadIdx.x, w = tid >> 5, t = tid & 31, r = blockIdx.x;

    if (tid < 66) {
        float a = 0.f;
        #pragma unroll
        for (int c = 0; c < 16; ++c) a += g_qpart[(r * 16 + c) * 68 + tid];
        sqa[tid] = a;
    }
    __syncthreads();
    if (tid < 64) {
        float Pmu = sqa[64], Pc = sqa[65];
        sqa[tid] = (lng[tid] * (sqa[tid] - Pmu) + lnb[tid] * Pc) / (Pc + 1e-10f);
    }
    __syncthreads();
    if (tid < 64) {
        float acc = 0.f;
        #pragma unroll
        for (int d = 0; d < 64; ++d) acc += sqa[d] * Wq[d * 64 + tid];
        sq[tid] = acc * 0.35355339059327373f;
    }
    __syncthreads();

    float mx[8];
    #pragma unroll
    for (int h = 0; h < 8; ++h) mx[h] = -3.0e38f;
    for (int s = tid; s < SS; s += 256) {
        float kk[8];
        #pragma unroll
        for (int c = 0; c < 8; ++c) kk[c] = g_kv[((r * 16 + c) * SS) + s];
        float bias = 1e9f * (g_maskT[r * SS + s] - 1.f);
        #pragma unroll
        for (int h = 0; h < 8; ++h) {
            float lg = bias;
            #pragma unroll
            for (int c = 0; c < 8; ++c) lg += sq[h * 8 + c] * kk[c];
            mx[h] = fmaxf(mx[h], lg);
        }
    }
    #pragma unroll
    for (int h = 0; h < 8; ++h) {
        #pragma unroll
        for (int o = 16; o > 0; o >>= 1) mx[h] = fmaxf(mx[h], __shfl_xor_sync(0xffffffffu, mx[h], o));
    }
    if (t < 8) red[w][t] = mx[t];
    __syncthreads();
    if (tid < 8) {
        float m = red[0][tid];
        #pragma unroll
        for (int ww = 1; ww < 8; ++ww) m = fmaxf(m, red[ww][tid]);
        smax[tid] = m;
    }
    __syncthreads();

    float Z[8];
    float acc[64];
    #pragma unroll
    for (int h = 0; h < 8; ++h) Z[h] = 0.f;
    #pragma unroll
    for (int i = 0; i < 64; ++i) acc[i] = 0.f;
    for (int s = tid; s < SS; s += 256) {
        float kk[8], vv[8];
        #pragma unroll
        for (int c = 0; c < 8; ++c) kk[c] = g_kv[((r * 16 + c) * SS) + s];
        #pragma unroll
        for (int c = 0; c < 8; ++c) vv[c] = g_kv[((r * 16 + 8 + c) * SS) + s];
        float bias = 1e9f * (g_maskT[r * SS + s] - 1.f);
        #pragma unroll
        for (int h = 0; h < 8; ++h) {
            float lg = bias;
            #pragma unroll
            for (int c = 0; c < 8; ++c) lg += sq[h * 8 + c] * kk[c];
            float e = __expf(lg - smax[h]);
            Z[h] += e;
            #pragma unroll
            for (int c = 0; c < 8; ++c) acc[h * 8 + c] += e * vv[c];
        }
    }
    #pragma unroll
    for (int i = 0; i < 64; ++i) {
        float v = acc[i];
        #pragma unroll
        for (int o = 16; o > 0; o >>= 1) v += __shfl_xor_sync(0xffffffffu, v, o);
        if (t == 0) red[w][i] = v;
    }
    #pragma unroll
    for (int h = 0; h < 8; ++h) {
        float v = Z[h];
        #pragma unroll
        for (int o = 16; o > 0; o >>= 1) v += __shfl_xor_sync(0xffffffffu, v, o);
        if (t == 0) red[w][64 + h] = v;
    }
    __syncthreads();
    if (tid < 72) {
        float v = 0.f;
        #pragma unroll
        for (int ww = 0; ww < 8; ++ww) v += red[ww][tid];
        red[0][tid] = v;
    }
    __syncthreads();
    if (tid < 64) g_o[r * 64 + tid] = red[0][tid] / red[0][64 + (tid >> 3)];
}

// ---------------------------------------------------------------------------
// Kernel C (warp-MMA tf32, v3): block = fixed r, 2 tiles of 64 s-rows.
// B frags via __ldg (L1/L2-hot, 32KB shared by all blocks) -> smem 35KB
// -> 5 CTAs/SM. Epilogue2 stores straight to gmem (aligned 32B sectors).
// ---------------------------------------------------------------------------
__global__ __launch_bounds__(128) void kernelC(
    const float* __restrict__ M, const float* __restrict__ bov,
    float* __restrict__ outp, int sbase)
{
    __shared__ __align__(16) float XT[64 * 68];   // exact x tile
    __shared__ __align__(16) float GT[64 * 68];   // ghat (tf32 bits)
    __shared__ float soo[64], sS1g[64], sbG[64], sbo[64];

    const int tid = threadIdx.x, wid = tid >> 5, lid = tid & 31;
    const int g = lid >> 2, tg = lid & 3;
    const int r = blockIdx.y;
    const int xb = sbase + blockIdx.x;

    if (tid < 64) {
        soo[tid]  = g_o[r * 64 + tid];
        sS1g[tid] = g_S1g[tid];
        sbG[tid]  = g_bG[tid];
        sbo[tid]  = bov[tid];
    }
    __syncthreads();

    const int arow = wid * 16 + g;

    for (int t = 0; t < 2; ++t) {
        const int s0 = (xb * 2 + t) * 64;
        // warp-local tile load (warp owns rows [wid*16, wid*16+16))
        #pragma unroll
        for (int it = 0; it < 8; ++it) {
            int f = lid + it * 32;
            int row = wid * 16 + (f >> 4), c4 = (f & 15) * 4;
            *(float4*)&XT[row * 68 + c4] =
                *(const float4*)&M[(((size_t)(s0 + row)) * RR + r) * 64 + c4];
        }
        __syncwarp();

        const float2 st0 = g_stats[(size_t)r * SS + s0 + arow];
        const float2 st1 = g_stats[(size_t)r * SS + s0 + arow + 8];

        uint32_t af[8][4];
        #pragma unroll
        for (int k = 0; k < 8; ++k) {
            af[k][0] = f2tf32(XT[arow * 68 + k * 8 + tg]);
            af[k][1] = f2tf32(XT[(arow + 8) * 68 + k * 8 + tg]);
            af[k][2] = f2tf32(XT[arow * 68 + k * 8 + tg + 4]);
            af[k][3] = f2tf32(XT[(arow + 8) * 68 + k * 8 + tg + 4]);
        }
        // ---- GEMM1 + sigmoid gate epilogue -> GT ----
        #pragma unroll
        for (int n = 0; n < 8; ++n) {
            float d4[4] = {0.f, 0.f, 0.f, 0.f};
            uint4 q0 = __ldg(&g_BP1[n * 32 + lid]);
            uint4 q1 = __ldg(&g_BP1[256 + n * 32 + lid]);
            uint4 q2 = __ldg(&g_BP1[512 + n * 32 + lid]);
            uint4 q3 = __ldg(&g_BP1[768 + n * 32 + lid]);
            mma_tf32(d4, af[0], q0.x, q0.y); mma_tf32(d4, af[1], q0.z, q0.w);
            mma_tf32(d4, af[2], q1.x, q1.y); mma_tf32(d4, af[3], q1.z, q1.w);
            mma_tf32(d4, af[4], q2.x, q2.y); mma_tf32(d4, af[5], q2.z, q2.w);
            mma_tf32(d4, af[6], q3.x, q3.y); mma_tf32(d4, af[7], q3.z, q3.w);
            const int j0 = n * 8 + 2 * tg;
            const float s1a = sS1g[j0], s1b = sS1g[j0 + 1];
            const float bga = sbG[j0],  bgb = sbG[j0 + 1];
            const float oa  = soo[j0],  ob  = soo[j0 + 1];
            float g00 = oa / (1.f + __expf(-(st0.y * (d4[0] - st0.x * s1a) + bga)));
            float g01 = ob / (1.f + __expf(-(st0.y * (d4[1] - st0.x * s1b) + bgb)));
            float g10 = oa / (1.f + __expf(-(st1.y * (d4[2] - st1.x * s1a) + bga)));
            float g11 = ob / (1.f + __expf(-(st1.y * (d4[3] - st1.x * s1b) + bgb)));
            *(uint2*)&GT[arow * 68 + j0]       = make_uint2(f2tf32(g00), f2tf32(g01));
            *(uint2*)&GT[(arow + 8) * 68 + j0] = make_uint2(f2tf32(g10), f2tf32(g11));
        }
        __syncwarp();

        // ---- GEMM2 A frags (ghat, already tf32 bits) ----
        {
            const uint32_t* GTu = (const uint32_t*)GT;
            #pragma unroll
            for (int k = 0; k < 8; ++k) {
                af[k][0] = GTu[arow * 68 + k * 8 + tg];
                af[k][1] = GTu[(arow + 8) * 68 + k * 8 + tg];
                af[k][2] = GTu[arow * 68 + k * 8 + tg + 4];
                af[k][3] = GTu[(arow + 8) * 68 + k * 8 + tg + 4];
            }
        }
        __syncwarp();
        // ---- GEMM2 + bias + exact residual -> direct gmem store ----
        float* o0p = &outp[(((size_t)(s0 + arow)) * RR + r) * 64];
        float* o1p = &outp[(((size_t)(s0 + arow + 8)) * RR + r) * 64];
        #pragma unroll
        for (int n = 0; n < 8; ++n) {
            float d4[4] = {0.f, 0.f, 0.f, 0.f};
            uint4 q0 = __ldg(&g_BP2[n * 32 + lid]);
            uint4 q1 = __ldg(&g_BP2[256 + n * 32 + lid]);
            uint4 q2 = __ldg(&g_BP2[512 + n * 32 + lid]);
            uint4 q3 = __ldg(&g_BP2[768 + n * 32 + lid]);
            mma_tf32(d4, af[0], q0.x, q0.y); mma_tf32(d4, af[1], q0.z, q0.w);
            mma_tf32(d4, af[2], q1.x, q1.y); mma_tf32(d4, af[3], q1.z, q1.w);
            mma_tf32(d4, af[4], q2.x, q2.y); mma_tf32(d4, af[5], q2.z, q2.w);
            mma_tf32(d4, af[6], q3.x, q3.y); mma_tf32(d4, af[7], q3.z, q3.w);
            const int c0 = n * 8 + 2 * tg;
            float2 x0 = *(const float2*)&XT[arow * 68 + c0];
            float2 x1 = *(const float2*)&XT[(arow + 8) * 68 + c0];
            *(float2*)&o0p[c0] =
                make_float2(d4[0] + sbo[c0] + x0.x, d4[1] + sbo[c0 + 1] + x0.y);
            *(float2*)&o1p[c0] =
                make_float2(d4[2] + sbo[c0] + x1.x, d4[3] + sbo[c0 + 1] + x1.y);
        }
        __syncwarp();  // XT/GT reuse barrier before next tile
    }
}

// ---------------------------------------------------------------------------
extern "C" void kernel_launch(void* const* d_in, const int* in_sizes, int n_in,
                              void* d_out, int out_size)
{
    (void)in_sizes; (void)n_in; (void)out_size;
    const float* M    = (const float*)d_in[0];
    const float* mask = (const float*)d_in[1];
    const float* ln_g = (const float*)d_in[2];
    const float* ln_b = (const float*)d_in[3];
    const float* Wq   = (const float*)d_in[4];
    const float* Wk   = (const float*)d_in[5];
    const float* Wv   = (const float*)d_in[6];
    const float* Wg   = (const float*)d_in[7];
    const float* bg   = (const float*)d_in[8];
    const float* Wo   = (const float*)d_in[9];
    const float* bo   = (const float*)d_in[10];
    float* outp = (float*)d_out;

    kernelDP<<<769, 256>>>(mask, ln_g, ln_b, Wk, Wv, Wg, bg, Wo);
    kernelA<<<dim3(16, 384), 128>>>(M);
    kernelB<<<384, 256>>>(Wq, ln_g, ln_b);
    kernelC<<<dim3(6, 384), 128>>>(M, bo, outp, 0);
    kernelC<<<dim3(5, 384), 128>>>(M, bo, outp, 6);
    kernelC<<<dim3(5, 384), 128>>>(M, bo, outp, 11);
}